// round 17
// baseline (speedup 1.0000x reference)
#include <cuda_runtime.h>

#define NH 192            // nH = nW = 193 - 2 + 1
#define HG 193            // grid H/W
#define MD 64             // vec dim m

// Scratch (allocation-free rule: __device__ globals)
__device__ float g_x[NH * NH * MD];      // x = win_avg(grid) @ M^T, 9.4 MB

// ---- packed f32x2 helpers (used only in x_prep, which is proven) -----------
__device__ __forceinline__ unsigned long long pk(float x, float y) {
    unsigned long long r;
    asm("mov.b64 %0, {%1, %2};" : "=l"(r) : "f"(x), "f"(y));
    return r;
}
__device__ __forceinline__ float2 upk(unsigned long long v) {
    float2 t;
    asm("mov.b64 {%0, %1}, %2;" : "=f"(t.x), "=f"(t.y) : "l"(v));
    return t;
}
__device__ __forceinline__ unsigned long long fma2(unsigned long long a,
                                                   unsigned long long b,
                                                   unsigned long long c) {
    unsigned long long r;
    asm("fma.rn.f32x2 %0, %1, %2, %3;" : "=l"(r) : "l"(a), "l"(b), "l"(c));
    return r;
}

// ---- cp.async helpers -------------------------------------------------------
__device__ __forceinline__ void cp_async16(unsigned dst_smem, const void* src) {
    asm volatile("cp.async.cg.shared.global [%0], [%1], 16;"
                 :: "r"(dst_smem), "l"(src) : "memory");
}
__device__ __forceinline__ void cp_commit() {
    asm volatile("cp.async.commit_group;" ::: "memory");
}
template <int N>
__device__ __forceinline__ void cp_wait() {
    asm volatile("cp.async.wait_group %0;" :: "n"(N) : "memory");
}

// ---------------------------------------------------------------------------
// Kernel 1: x[b, j] = sum_l wavg[b, l] * M[j, l]   (proven ~7us)
// ---------------------------------------------------------------------------
__global__ void __launch_bounds__(256) x_prep(const float* __restrict__ grid,
                                              const float* __restrict__ Mw) {
    __shared__ __align__(16) float sbuf[66 * 64];

    int t  = threadIdx.x;
    int q  = t >> 6;
    int jl = t & 63;

    int bid    = blockIdx.x;
    int k1     = bid / 6;
    int k2base = (bid % 6) * 32;

    for (int e = t; e < 4096; e += 256) sbuf[(e >> 6) * 66 + (e & 63)] = Mw[e];
    __syncthreads();
    unsigned long long Mp[32];
#pragma unroll
    for (int l = 0; l < 32; l++)
        Mp[l] = pk(sbuf[jl * 66 + 2 * l], sbuf[jl * 66 + 2 * l + 1]);
    __syncthreads();

#pragma unroll
    for (int r = 0; r < 8; r++) {
        int e   = t + 256 * r;
        int row = e >> 6;
        int col = e & 63;
        const float* g00 = grid + ((k1 * HG + k2base + row) * MD) + col;
        sbuf[row * 64 + col] = 0.25f * (g00[0] + g00[MD] +
                                        g00[HG * MD] + g00[HG * MD + MD]);
    }
    __syncthreads();

#pragma unroll
    for (int r = 0; r < 8; r++) {
        int k2r = q + 4 * r;
        const ulonglong2* w2 = reinterpret_cast<const ulonglong2*>(&sbuf[k2r * 64]);
        unsigned long long a0 = 0ULL, a1 = 0ULL;
#pragma unroll
        for (int l = 0; l < 16; l++) {
            ulonglong2 w = w2[l];
            a0 = fma2(Mp[2 * l],     w.x, a0);
            a1 = fma2(Mp[2 * l + 1], w.y, a1);
        }
        float2 f0 = upk(a0), f1 = upk(a1);
        g_x[(k1 * NH + k2base + k2r) * MD + jl] = (f0.x + f0.y) + (f1.x + f1.y);
    }
}

// ---------------------------------------------------------------------------
// Main kernel — scalar Chebyshev, CROSSBAR-OPTIMIZED layout:
//   d_{k+1} = tc*d_k - d_{k-1}  (free neg modifier), ping-pong, zero copies.
//
// 512 threads: t = (k1sub<<8) | (ip<<3) | jo.
//   Each thread owns TWO i (ip, ip+32) x EIGHT j (jo*8..+8): the 8 x floats
//   loaded per step (2 LDS.128) feed BOTH i-chains -> half the LDS of R16.
//   Chains: tc[16], A[16], B[16] = 48 regs (c<8: i=ip; c>=8: i=ip+32).
// xs layout: j-slice stride 12 words -> slice banks {0,12,24,4,16,28,8,20}+0..3
//   = all 32 banks distinct -> ZERO bank conflicts (R16 had 2-way).
// __launch_bounds__(512,2): 32 warps/SM; grid (3,96) = 288 CTAs = one wave.
// jo-lanes reduced with 3 shfl_xor per output (6 total); jo==0 stores.
// ---------------------------------------------------------------------------
__global__ void __launch_bounds__(512, 2) main_kernel(const float* __restrict__ P,
                                                      float* __restrict__ out) {
    __shared__ __align__(16) float xs[2][16][2][96];     // 24 KB (12-word slices)

    int t      = threadIdx.x;
    int jo     = t & 7;                  // 8-j slice
    int ip     = (t >> 3) & 31;          // i = ip and ip+32
    int k1sub  = t >> 8;                 // 0..1
    int k1base = blockIdx.y * 2;
    int k1     = k1base + k1sub;
    int k2s    = blockIdx.x * 64;

    unsigned xs_base = (unsigned)__cvta_generic_to_shared(&xs[0][0][0][0]);

    // stage one 16-k2 block of x: 512 float4s, one per thread, strided dst
    auto issue_block = [&](int b) {
        int kb = k2s + b * 16;
        unsigned dbase = xs_base + ((b & 1) ? 12288u : 0u);
        int s  = t >> 8;                             // k1 row 0..1
        int r  = (t >> 4) & 15;                      // k2 offset 0..15
        int j4 = t & 15;                             // float4 group 0..15
        const float4* src = reinterpret_cast<const float4*>(g_x) +
                            (((k1base + s) * NH + kb + r) << 4) + j4;
        unsigned dst = dbase +
            (((r * 2 + s) * 96 + (j4 >> 1) * 12 + (j4 & 1) * 4) << 2);
        cp_async16(dst, src);
        cp_commit();
    };

    issue_block(0);          // overlap staging with the cosf-heavy prologue
    issue_block(1);

    // ---- prologue: inline cos; chains for (ip, jo-slice) and (ip+32, jo-slice)
    float tc[16], A[16], B[16];
    {
        const float TWO_PI = 6.2831853071795864769f;
        float k1f = (float)k1;
        float kaf = (float)k2s;
        float kbf = (float)(k2s - 1);                // cos even: handles k2s=0
#pragma unroll
        for (int h = 0; h < 2; h++) {                // h=0: i=ip, h=1: i=ip+32
            int iv = ip + h * 32;
#pragma unroll
            for (int c = 0; c < 8; c++) {
                int j = jo * 8 + c;
                float Tj = (float)(iv * MD + j + 2);
                float w  = TWO_PI / Tj;
                float e  = cosf(w * k1f) * P[iv * MD + j];   // E = P * cos1
                A[8 * h + c]  = e * cosf(w * kaf);   // d_{k2s}
                B[8 * h + c]  = e * cosf(w * kbf);   // d_{k2s-1}
                tc[8 * h + c] = 2.0f * cosf(w);      // 2 cos(theta)
            }
        }
    }

    float* obase = out + (k1 * NH + k2s) * MD + ip;

    // one k2 step: acc both i with chain C; advance D = tc*C - D (ping-pong)
#define STEP(C, D, ROFF, XB)                                                \
    {                                                                       \
        const float4* xr =                                                  \
            reinterpret_cast<const float4*>((XB) + (ROFF) * 192 + jo * 12); \
        float4 x0 = xr[0];                                                  \
        float4 x1 = xr[1];                                                  \
        float pa0 = C[0] * x0.x,  pa1 = C[1] * x0.y;                        \
        pa0 = fmaf(C[2], x0.z, pa0);  pa1 = fmaf(C[3], x0.w, pa1);          \
        pa0 = fmaf(C[4], x1.x, pa0);  pa1 = fmaf(C[5], x1.y, pa1);          \
        pa0 = fmaf(C[6], x1.z, pa0);  pa1 = fmaf(C[7], x1.w, pa1);          \
        float pb0 = C[8] * x0.x,  pb1 = C[9] * x0.y;                        \
        pb0 = fmaf(C[10], x0.z, pb0); pb1 = fmaf(C[11], x0.w, pb1);         \
        pb0 = fmaf(C[12], x1.x, pb0); pb1 = fmaf(C[13], x1.y, pb1);         \
        pb0 = fmaf(C[14], x1.z, pb0); pb1 = fmaf(C[15], x1.w, pb1);         \
        _Pragma("unroll")                                                   \
        for (int c = 0; c < 16; c++) D[c] = fmaf(tc[c], C[c], -D[c]);       \
        float pa = pa0 + pa1;                                               \
        float pb = pb0 + pb1;                                               \
        pa += __shfl_xor_sync(0xFFFFFFFFu, pa, 1);                          \
        pb += __shfl_xor_sync(0xFFFFFFFFu, pb, 1);                          \
        pa += __shfl_xor_sync(0xFFFFFFFFu, pa, 2);                          \
        pb += __shfl_xor_sync(0xFFFFFFFFu, pb, 2);                          \
        pa += __shfl_xor_sync(0xFFFFFFFFu, pa, 4);                          \
        pb += __shfl_xor_sync(0xFFFFFFFFu, pb, 4);                          \
        if (jo == 0) {                                                      \
            obase[(b * 16 + (ROFF)) * MD]      = pa;                        \
            obase[(b * 16 + (ROFF)) * MD + 32] = pb;                        \
        }                                                                   \
    }

    // ---- main loop: 4 blocks x 16 k2 (2-step ping-pong, zero copies) ----
    for (int b = 0; b < 4; b++) {
        if (b >= 1) {
            __syncthreads();             // readers of buf[(b+1)&1] (block b-1) done
            if (b + 1 < 4) issue_block(b + 1);
        }
        if (b + 1 < 4) cp_wait<1>(); else cp_wait<0>();
        __syncthreads();                 // block b visible to all

        const float* xb = &xs[b & 1][0][k1sub][0];

#pragma unroll
        for (int r = 0; r < 8; r++) {
            STEP(A, B, 2 * r,     xb)    // acc d_k;     B <- d_{k+1}
            STEP(B, A, 2 * r + 1, xb)    // acc d_{k+1}; A <- d_{k+2}
        }
    }
#undef STEP
}

// ---------------------------------------------------------------------------
// Launch: inputs in metadata order: grid [193,193,64], M_weight [64,64], P [64,64]
// ---------------------------------------------------------------------------
extern "C" void kernel_launch(void* const* d_in, const int* in_sizes, int n_in,
                              void* d_out, int out_size) {
    const float* grid = (const float*)d_in[0];
    const float* Mw   = (const float*)d_in[1];
    const float* P    = (const float*)d_in[2];
    float* out        = (float*)d_out;

    x_prep<<<1152, 256>>>(grid, Mw);
    main_kernel<<<dim3(3, 96), 512>>>(P, out);
}